// round 12
// baseline (speedup 1.0000x reference)
#include <cuda_runtime.h>
#include <cstdint>

#define IN_DIM   128
#define H_DIM    256
#define M_DIM    32
#define K_TOT    384
#define TILE_M   128
#define TILE_N   128
#define KC       32            // fp32 per row per chunk = 128B rows
#define NCHUNK   12
#define THREADS  256

// ---- SMEM: two 32KB stage buffers (A 16KB | W 16KB), then m-gate tile ----
#define OFF_A    0
#define OFF_W    16384
#define SM_BUF0  0
#define SM_BUF1  32768
#define SM_M     65536
#define SM_MSTRIDE 272
#define SM_TOTAL (SM_M + TILE_M*SM_MSTRIDE)   // 100352

// compensation for tf32 truncation (2 operands): 1 + ~2*E[rel shrink]
#define COMP 1.000677f

static __device__ __forceinline__ uint32_t smem_u32(const void* p) {
    uint32_t a;
    asm("{ .reg .u64 t; cvta.to.shared.u64 t, %1; cvt.u32.u64 %0, t; }" : "=r"(a) : "l"(p));
    return a;
}
static __device__ __forceinline__ void ldsm4(uint32_t* r, uint32_t addr) {
    asm volatile("ldmatrix.sync.aligned.m8n8.x4.shared.b16 {%0,%1,%2,%3}, [%4];"
                 : "=r"(r[0]), "=r"(r[1]), "=r"(r[2]), "=r"(r[3]) : "r"(addr));
}
static __device__ __forceinline__ void mma_tf32(float* d, const uint32_t* a, const uint32_t* b) {
    asm volatile("mma.sync.aligned.m16n8k8.row.col.f32.tf32.tf32.f32 "
                 "{%0,%1,%2,%3}, {%4,%5,%6,%7}, {%8,%9}, {%0,%1,%2,%3};"
                 : "+f"(d[0]), "+f"(d[1]), "+f"(d[2]), "+f"(d[3])
                 : "r"(a[0]), "r"(a[1]), "r"(a[2]), "r"(a[3]), "r"(b[0]), "r"(b[1]));
}
#define CP16(dst, src) \
    asm volatile("cp.async.cg.shared.global [%0], [%1], 16;" \
                 :: "r"(dst), "l"(src) : "memory")
#define CPCOMMIT() asm volatile("cp.async.commit_group;" ::: "memory")
#define CPWAIT(n)  asm volatile("cp.async.wait_group %0;" :: "n"(n) : "memory")

__global__ __launch_bounds__(THREADS, 2)
void rlstm_kernel(const float* __restrict__ inp, const float* __restrict__ media,
                  const float* __restrict__ h_t, const float* __restrict__ c_t,
                  const float* __restrict__ Wi, const float* __restrict__ bi,
                  const float* __restrict__ Wm, const float* __restrict__ bm,
                  float* __restrict__ out, int Btot) {
    extern __shared__ char sm[];
    const uint32_t sb = smem_u32(sm);
    const int tid = threadIdx.x;
    const int lid = tid & 31;
    const int wid = tid >> 5;
    const int wm = wid & 3;          // 4 warp-rows x 32 = 128 M
    const int wn = wid >> 2;         // 2 warp-cols x 64 = 128 N
    const int m0 = (int)(blockIdx.x >> 1) * TILE_M;
    const int n0 = (int)(blockIdx.x & 1) * TILE_N;

    // ---- cp.async loader coords: 256 thr x 16B = 4KB/pass; 4 passes per 16KB tile
    const int l_row  = tid >> 3;           // +32 per pass; (row & 7) invariant
    const int l_unit = tid & 7;
    const uint32_t l_su = (uint32_t)(l_unit ^ (l_row & 7)) << 4;   // swizzled 16B unit

    // ---- ldmatrix per-lane components (tf32 via b16 pair trick) ----
    const int ai = lid & 7;
    const int atile = lid >> 3;
    const int arow_off = (atile & 1) * 8 + ai;       // + wm*32 + mb*16
    const int aub = atile >> 1;
    const int wtile = lid >> 3;
    const int wrow_off = (wtile >> 1) * 8 + ai;      // + wn*64 + nb2*16
    const int wub = wtile & 1;

    // separate k-offsets for A and W — they differ once A switches to h_t.
    auto cp_chunk = [&](uint32_t buf, const float* asrc, int astride, int akk,
                        const float* wsrc, int wstride, int wkk) {
        #pragma unroll
        for (int it = 0; it < 4; it++) {
            int row = l_row + it * 32;
            uint32_t dst = sb + buf + (uint32_t)row * 128u + l_su;
            CP16(dst + OFF_A, asrc + (size_t)row * astride + akk + l_unit * 4);
            CP16(dst + OFF_W, wsrc + (size_t)row * wstride + wkk + l_unit * 4);
        }
        CPCOMMIT();
    };
    auto cp_main = [&](int ch) {
        uint32_t buf = (ch & 1) ? SM_BUF0 : SM_BUF1;     // chunk ch lands here
        if (ch < 4)
            cp_chunk(buf, inp + (size_t)m0 * IN_DIM, IN_DIM, ch * KC,
                          Wi + (size_t)n0 * K_TOT, K_TOT, ch * KC);
        else
            cp_chunk(buf, h_t + (size_t)m0 * H_DIM, H_DIM, (ch - 4) * KC,
                          Wi + (size_t)n0 * K_TOT, K_TOT, ch * KC);
    };

    float d[2][8][4];
    auto zero_d = [&]() {
        #pragma unroll
        for (int mb = 0; mb < 2; mb++)
            #pragma unroll
            for (int nb = 0; nb < 8; nb++)
                #pragma unroll
                for (int j = 0; j < 4; j++) d[mb][nb][j] = 0.f;
    };

    // W-fragment double-buffered: ldsm for nb2+1 issues before nb2's MMAs
    auto run_chunk = [&](uint32_t buf) {
        const uint32_t bA = sb + buf + OFF_A;
        const uint32_t bW = sb + buf + OFF_W;
        #pragma unroll
        for (int s = 0; s < 4; s++) {            // 4 k8-steps = KC 32
            uint32_t a[2][4], t[2][4];
            #pragma unroll
            for (int mb = 0; mb < 2; mb++) {
                int row = wm * 32 + mb * 16 + arow_off;
                uint32_t u = (uint32_t)((2 * s + aub) ^ ai) << 4;
                ldsm4(a[mb], bA + (uint32_t)row * 128u + u);
            }
            {   // prime t[0] with nb2=0
                int row = wn * 64 + wrow_off;
                uint32_t u = (uint32_t)((2 * s + wub) ^ ai) << 4;
                ldsm4(t[0], bW + (uint32_t)row * 128u + u);
            }
            #pragma unroll
            for (int nb2 = 0; nb2 < 4; nb2++) {
                if (nb2 < 3) {
                    int row = wn * 64 + (nb2 + 1) * 16 + wrow_off;
                    uint32_t u = (uint32_t)((2 * s + wub) ^ ai) << 4;
                    ldsm4(t[(nb2 + 1) & 1], bW + (uint32_t)row * 128u + u);
                }
                const uint32_t* tc = t[nb2 & 1];
                mma_tf32(d[0][2*nb2],   a[0], tc);
                mma_tf32(d[0][2*nb2+1], a[0], tc + 2);
                mma_tf32(d[1][2*nb2],   a[1], tc);
                mma_tf32(d[1][2*nb2+1], a[1], tc + 2);
            }
        }
    };

    // ================= prologue =================
    cp_chunk(SM_BUF0, media + (size_t)m0 * M_DIM, M_DIM, 0,
                      Wm + (size_t)n0 * M_DIM, M_DIM, 0);           // group: media -> B0
    cp_main(0);                                                      // group: chunk0 -> B1
    CPWAIT(1);                     // media landed (chunk0 may be in flight)
    __syncthreads();
    zero_d();
    run_chunk(SM_BUF0);            // media GEMM (K=32)

    // sigmoid(media + bm) -> u16 fixed point in m-tile (same-thread write/read; no barrier)
    #pragma unroll
    for (int mb = 0; mb < 2; mb++)
        #pragma unroll
        for (int nb = 0; nb < 8; nb++) {
            int colg = n0 + wn * 64 + nb * 8 + (lid & 3) * 2;
            float2 bmv = *reinterpret_cast<const float2*>(bm + colg);
            #pragma unroll
            for (int jh = 0; jh < 2; jh++) {
                float x0 = fminf(fmaxf(d[mb][nb][jh*2+0] * COMP + bmv.x, -30.f), 30.f);
                float x1 = fminf(fmaxf(d[mb][nb][jh*2+1] * COMP + bmv.y, -30.f), 30.f);
                float g0 = __fdividef(1.f, 1.f + __expf(-x0));
                float g1 = __fdividef(1.f, 1.f + __expf(-x1));
                uint32_t q0 = __float2uint_rn(g0 * 65535.f);
                uint32_t q1 = __float2uint_rn(g1 * 65535.f);
                int rowl = wm * 32 + mb * 16 + (lid >> 2) + jh * 8;
                int cp   = wn * 32 + nb * 4 + (lid & 3);
                *reinterpret_cast<uint32_t*>(sm + SM_M + rowl * SM_MSTRIDE + cp * 4)
                    = q0 | (q1 << 16);
            }
        }
    zero_d();

    // ================= mainloop: 12 chunks, 2 buffers, ONE barrier per chunk =================
    // iter ch: wait chunk ch; barrier (also proves chunk ch-1 / media buffer consumed);
    //          issue cp for ch+1 into the freed buffer; run chunk ch.
    #pragma unroll 1
    for (int ch = 0; ch < NCHUNK; ch++) {
        CPWAIT(0);                               // my portion of chunk ch landed
        __syncthreads();                         // all portions landed; prev buffer free
        if (ch + 1 < NCHUNK) cp_main(ch + 1);    // full chunk duration to cover latency
        run_chunk((ch & 1) ? SM_BUF0 : SM_BUF1); // chunk ch lives here
    }

    // ================= epilogue =================
    const size_t BH = (size_t)Btot * H_DIM;
    #pragma unroll
    for (int mb = 0; mb < 2; mb++)
        #pragma unroll
        for (int nb = 0; nb < 8; nb++) {
            int colg = n0 + wn * 64 + nb * 8 + (lid & 3) * 2;
            float2 biv = *reinterpret_cast<const float2*>(bi + colg);
            #pragma unroll
            for (int jh = 0; jh < 2; jh++) {
                int rowl = wm * 32 + mb * 16 + (lid >> 2) + jh * 8;
                int rowg = m0 + rowl;
                int cp   = wn * 32 + nb * 4 + (lid & 3);
                uint32_t mq = *reinterpret_cast<const uint32_t*>(sm + SM_M + rowl * SM_MSTRIDE + cp * 4);
                float mg[2] = { (float)(mq & 0xFFFF) * (1.f / 65535.f),
                                (float)(mq >> 16)    * (1.f / 65535.f) };
                size_t o = (size_t)rowg * H_DIM + colg;
                float2 ct = *reinterpret_cast<const float2*>(c_t + o);
                float gr[2] = { d[mb][nb][jh*2+0] * COMP + biv.x,
                                d[mb][nb][jh*2+1] * COMP + biv.y };
                float ctv[2] = { ct.x, ct.y };
                float hv[2], cv[2];
                #pragma unroll
                for (int e = 0; e < 2; e++) {
                    float g = fminf(fmaxf(gr[e], -30.f), 30.f);
                    float ex = __expf(-g);
                    float gate = __fdividef(1.f, 1.f + ex);
                    float e2 = ex * ex;
                    float thg = __fdividef(1.f - e2, 1.f + e2);        // tanh(g)
                    float c = gate * (ctv[e] + thg);
                    float cc = fminf(fmaxf(c, -15.f), 15.f);
                    float ec = __expf(-2.f * cc);
                    float cr = __fdividef(1.f - ec, 1.f + ec);         // tanh(c)
                    float cf = c - cr + cr * mg[e];
                    float cfc = fminf(fmaxf(cf, -15.f), 15.f);
                    float ef = __expf(-2.f * cfc);
                    float thf = __fdividef(1.f - ef, 1.f + ef);        // tanh(c_f)
                    hv[e] = thf * gate;
                    cv[e] = c;
                }
                float2 hvv = make_float2(hv[0], hv[1]);
                float2 cvv = make_float2(cv[0], cv[1]);
                *reinterpret_cast<float2*>(out + o)          = hvv;
                *reinterpret_cast<float2*>(out + BH + o)     = hvv;
                *reinterpret_cast<float2*>(out + 2 * BH + o) = cvv;
            }
        }
}

extern "C" void kernel_launch(void* const* d_in, const int* in_sizes, int n_in,
                              void* d_out, int out_size) {
    const float* inp   = (const float*)d_in[0];
    const float* media = (const float*)d_in[1];
    const float* h_t   = (const float*)d_in[2];
    const float* c_t   = (const float*)d_in[3];
    const float* Wi    = (const float*)d_in[4];
    const float* bi    = (const float*)d_in[5];
    const float* Wm    = (const float*)d_in[6];
    const float* bm    = (const float*)d_in[7];
    int B = in_sizes[0] / IN_DIM;

    cudaFuncSetAttribute(rlstm_kernel, cudaFuncAttributeMaxDynamicSharedMemorySize, SM_TOTAL);
    dim3 grid((B / TILE_M) * 2);
    rlstm_kernel<<<grid, THREADS, SM_TOTAL>>>(inp, media, h_t, c_t, Wi, bi, Wm, bm,
                                              (float*)d_out, B);
}